// round 2
// baseline (speedup 1.0000x reference)
#include <cuda_runtime.h>
#include <cuda_bf16.h>
#include <math.h>

// ---------------- model dims ----------------
#define BS   64
#define T    96
#define C    16
#define INF_ 16
#define H    256
#define NH   8
#define DH   32
#define NCLS 4
#define L    100           // T + NCLS
#define LAYERS 4
#define M_ROWS (1024*100)  // (BS*C) * L = 102400
#define SEQS   1024        // BS*C

// ---------------- scratch (device globals; no allocation allowed) ----------------
__device__ float d_h   [26214400];   // (1024,100,256)
__device__ float d_qkv [78643200];   // (1024,100,768)
__device__ float d_attn[26214400];   // (1024,100,256)
__device__ float d_tmp [104857600];  // (1024,100,1024) -- also reused for 256-wide outputs
__device__ float d_a   [256];        // normalized adjacency (16x16)
__device__ float d_X   [1048576];    // (64,16,4,256) cls extract
__device__ float d_H1  [1048576];
__device__ float d_H2  [1048576];
__device__ float d_d1  [16384];      // (64,256)

// ---------------- embedding ----------------
// h[s,l,o] = (l<T ? x[b,l,c,:]@Wfc[o,:]+bfc[o] : cls[l-T,c,o]) + pos[l,c,o]
__global__ void k_embed(const float* __restrict__ x, const float* __restrict__ Wfc,
                        const float* __restrict__ bfc, const float* __restrict__ cls,
                        const float* __restrict__ pos, float* __restrict__ hout) {
    int r = blockIdx.x;           // s*100 + l
    int s = r / L, l = r % L;
    int b = s >> 4, c = s & 15;
    int o = threadIdx.x;
    float v;
    if (l < T) {
        const float* xr = x + (((size_t)(b*T + l))*C + c)*INF_;
        const float* wr = Wfc + o*INF_;
        float acc = bfc[o];
#pragma unroll
        for (int i = 0; i < INF_; i++) acc += xr[i]*wr[i];
        v = acc;
    } else {
        v = cls[((l - T)*C + c)*H + o];
    }
    v += pos[(l*C + c)*H + o];
    hout[(size_t)r*H + o] = v;
}

// ---------------- graph constructor (tiny, one block) ----------------
__global__ void k_graph(const float* __restrict__ emb1, const float* __restrict__ emb2,
                        const float* __restrict__ Wl1, const float* __restrict__ bl1,
                        const float* __restrict__ Wl2, const float* __restrict__ bl2,
                        float* __restrict__ a_out) {
    __shared__ float sm1[16][256];
    __shared__ float sm2[16][256];
    int o = threadIdx.x;
    for (int c = 0; c < 16; c++) {
        float s1 = bl1[o], s2 = bl2[o];
        const float* e1 = emb1 + c*256;
        const float* e2 = emb2 + c*256;
        const float* w1 = Wl1 + o*256;
        const float* w2 = Wl2 + o*256;
        for (int i = 0; i < 256; i++) { s1 += e1[i]*w1[i]; s2 += e2[i]*w2[i]; }
        sm1[c][o] = tanhf(s1); sm2[c][o] = tanhf(s2);
    }
    __syncthreads();
    int v = o >> 4, w = o & 15;
    float s = 0.f;
    for (int k = 0; k < 256; k++) s += sm1[v][k]*sm2[w][k] - sm2[v][k]*sm1[w][k];
    float adj = fmaxf(tanhf(s), 0.f) + ((v == w) ? 1.f : 0.f);
    __shared__ float sadj[256];
    __shared__ float srow[16];
    sadj[o] = adj;
    __syncthreads();
    if (o < 16) {
        float rs = 0.f;
        for (int j = 0; j < 16; j++) rs += sadj[o*16 + j];
        srow[o] = rs;
    }
    __syncthreads();
    a_out[o] = sadj[o] / srow[v];
}

// ---------------- SGEMM: C = A(MxK) @ B(NxK)^T + bias, optional relu ----------------
// 128x128 block, BK=16, 256 threads, 8x8 microtile. All dims are exact multiples.
__global__ __launch_bounds__(256) void k_gemm(const float* __restrict__ A,
                                              const float* __restrict__ B,
                                              const float* __restrict__ bias,
                                              float* __restrict__ Cmat,
                                              int M, int N, int K, int relu) {
    __shared__ float As[16][128];
    __shared__ float Bs[16][128];
    int tid = threadIdx.x;
    int m0 = blockIdx.y * 128;
    int n0 = blockIdx.x * 128;
    int tx = tid & 15, ty = tid >> 4;
    float acc[8][8];
#pragma unroll
    for (int i = 0; i < 8; i++)
#pragma unroll
        for (int j = 0; j < 8; j++) acc[i][j] = 0.f;

    for (int k0 = 0; k0 < K; k0 += 16) {
#pragma unroll
        for (int it = 0; it < 2; it++) {
            int f  = tid + it*256;         // 0..511
            int m  = f >> 2;
            int kq = f & 3;
            float4 va = *reinterpret_cast<const float4*>(A + (size_t)(m0 + m)*K + k0 + kq*4);
            As[kq*4+0][m] = va.x; As[kq*4+1][m] = va.y;
            As[kq*4+2][m] = va.z; As[kq*4+3][m] = va.w;
            float4 vb = *reinterpret_cast<const float4*>(B + (size_t)(n0 + m)*K + k0 + kq*4);
            Bs[kq*4+0][m] = vb.x; Bs[kq*4+1][m] = vb.y;
            Bs[kq*4+2][m] = vb.z; Bs[kq*4+3][m] = vb.w;
        }
        __syncthreads();
#pragma unroll
        for (int k = 0; k < 16; k++) {
            float4 a0 = *reinterpret_cast<const float4*>(&As[k][ty*8]);
            float4 a1 = *reinterpret_cast<const float4*>(&As[k][ty*8 + 4]);
            float4 b0 = *reinterpret_cast<const float4*>(&Bs[k][tx*8]);
            float4 b1 = *reinterpret_cast<const float4*>(&Bs[k][tx*8 + 4]);
            float ar[8] = {a0.x,a0.y,a0.z,a0.w,a1.x,a1.y,a1.z,a1.w};
            float br[8] = {b0.x,b0.y,b0.z,b0.w,b1.x,b1.y,b1.z,b1.w};
#pragma unroll
            for (int i = 0; i < 8; i++)
#pragma unroll
                for (int j = 0; j < 8; j++)
                    acc[i][j] += ar[i]*br[j];
        }
        __syncthreads();
    }
#pragma unroll
    for (int i = 0; i < 8; i++) {
        int row = m0 + ty*8 + i;
#pragma unroll
        for (int j = 0; j < 8; j++) {
            int col = n0 + tx*8 + j;
            float v = acc[i][j] + bias[col];
            if (relu) v = fmaxf(v, 0.f);
            Cmat[(size_t)row*N + col] = v;
        }
    }
}

// ---------------- fused attention (one block per (head, seq)) ----------------
__global__ void k_attn(const float* __restrict__ qkv, float* __restrict__ out) {
    int hh = blockIdx.x;     // head
    int s  = blockIdx.y;     // sequence
    int tid = threadIdx.x;   // 128 threads
    __shared__ float Ks[100][32];
    __shared__ float Vs[100][32];
    const float* base = qkv + (size_t)s*L*768;
    for (int idx = tid; idx < L*DH; idx += 128) {
        int l = idx >> 5, d = idx & 31;
        Ks[l][d] = base[l*768 + 256 + hh*DH + d];
        Vs[l][d] = base[l*768 + 512 + hh*DH + d];
    }
    __syncthreads();
    if (tid < L) {
        int lq = tid;
        float q[DH];
        const float* qp = base + lq*768 + hh*DH;
#pragma unroll
        for (int d = 0; d < DH; d++) q[d] = qp[d] * 0.17677669529663687f;  // 1/sqrt(32)
        int kmax = (lq >= T) ? L : (lq + 1);
        float m = -1e30f, sum = 0.f;
        float acc[DH];
#pragma unroll
        for (int d = 0; d < DH; d++) acc[d] = 0.f;
        for (int k = 0; k < kmax; k++) {
            float sc = 0.f;
#pragma unroll
            for (int d = 0; d < DH; d++) sc += q[d]*Ks[k][d];
            float mn = fmaxf(m, sc);
            float corr = expf(m - mn);
            float pr   = expf(sc - mn);
            sum = sum*corr + pr;
#pragma unroll
            for (int d = 0; d < DH; d++) acc[d] = acc[d]*corr + pr*Vs[k][d];
            m = mn;
        }
        float inv = 1.f/sum;
        float* op = out + ((size_t)s*L + lq)*H + hh*DH;
#pragma unroll
        for (int d = 0; d < DH; d++) op[d] = acc[d]*inv;
    }
}

// ---------------- residual add + LayerNorm (in-place on h) ----------------
__global__ void k_addln(float* __restrict__ h, const float* __restrict__ p,
                        const float* __restrict__ g, const float* __restrict__ b) {
    int r = blockIdx.x, o = threadIdx.x;
    size_t idx = (size_t)r*H + o;
    float v = h[idx] + p[idx];
    __shared__ float red[8];
    float s = v;
#pragma unroll
    for (int off = 16; off > 0; off >>= 1) s += __shfl_down_sync(0xffffffffu, s, off);
    int lane = o & 31, wid = o >> 5;
    if (lane == 0) red[wid] = s;
    __syncthreads();
    if (o == 0) {
        float t = 0.f;
        for (int i = 0; i < 8; i++) t += red[i];
        red[0] = t * (1.f/H);
    }
    __syncthreads();
    float mean = red[0];
    __syncthreads();
    float d = v - mean;
    s = d*d;
#pragma unroll
    for (int off = 16; off > 0; off >>= 1) s += __shfl_down_sync(0xffffffffu, s, off);
    if (lane == 0) red[wid] = s;
    __syncthreads();
    if (o == 0) {
        float t = 0.f;
        for (int i = 0; i < 8; i++) t += red[i];
        red[0] = rsqrtf(t * (1.f/H) + 1e-5f);
    }
    __syncthreads();
    float rstd = red[0];
    h[idx] = d*rstd*g[o] + b[o];
}

// ---------------- mixprop pieces ----------------
__global__ void k_extract(const float* __restrict__ h, float* __restrict__ X) {
    int b = blockIdx.x;          // (n*16+w)*4 + lc, 4096 blocks
    int ch = threadIdx.x;
    int lc = b & 3, sw = b >> 2;
    X[(size_t)b*H + ch] = h[(size_t)sw*(L*H) + (T + lc)*H + ch];
}

__global__ void k_prop(const float* __restrict__ a, const float* __restrict__ in,
                       float* __restrict__ out) {
    __shared__ float sa[256];
    int tid = threadIdx.x;
    sa[tid] = a[tid];
    __syncthreads();
    int b = blockIdx.x;          // (n,v,lc)
    int lc = b & 3, v = (b >> 2) & 15, n = b >> 6;
    float acc = 0.f;
#pragma unroll
    for (int w = 0; w < 16; w++)
        acc += sa[v*16 + w] * in[((size_t)(n*16 + w)*4 + lc)*H + tid];
    out[(size_t)b*H + tid] = acc;
}

__global__ void k_mixout(const float* __restrict__ X, const float* __restrict__ H1,
                         const float* __restrict__ H2, const float* __restrict__ Wm,
                         const float* __restrict__ bm, float* __restrict__ h) {
    __shared__ float row[768];
    int b = blockIdx.x, o = threadIdx.x;
    row[o]       = X [(size_t)b*H + o];
    row[256 + o] = H1[(size_t)b*H + o];
    row[512 + o] = H2[(size_t)b*H + o];
    __syncthreads();
    const float* wr = Wm + (size_t)o*768;
    float acc = bm[o];
    for (int ch = 0; ch < 768; ch++) acc += wr[ch]*row[ch];
    int lc = b & 3, sw = b >> 2;
    h[(size_t)sw*(L*H) + (T + lc)*H + o] = acc;
}

// ---------------- decoder ----------------
__global__ void k_dec1(const float* __restrict__ h, const float* __restrict__ Wd1,
                       const float* __restrict__ bd1, float* __restrict__ d1) {
    __shared__ float zc[1024];
    int n = blockIdx.x, o = threadIdx.x;
    float acc = 0.f;
    for (int c = 0; c < 16; c++) {
        const float* hp = h + (size_t)(n*16 + c)*(L*H) + T*H;   // 4 cls rows = 1024 contiguous
        for (int jj = o; jj < 1024; jj += 256) zc[jj] = tanhf(hp[jj]);
        __syncthreads();
        const float* wr = Wd1 + (size_t)o*16384 + c*1024;
        float a = 0.f;
        for (int jj = 0; jj < 1024; jj++) a += wr[jj]*zc[jj];
        acc += a;
        __syncthreads();
    }
    acc += bd1[o];
    d1[n*H + o] = 0.5f*acc*(1.f + erff(acc*0.70710678118654752f));   // exact gelu
}

__global__ void k_dec2(const float* __restrict__ d1, const float* __restrict__ Wd2,
                       const float* __restrict__ bd2, float* __restrict__ out) {
    int n = blockIdx.x, tid = threadIdx.x;
    float v = d1[n*H + tid]*Wd2[tid];
    __shared__ float red[8];
#pragma unroll
    for (int off = 16; off > 0; off >>= 1) v += __shfl_down_sync(0xffffffffu, v, off);
    if ((tid & 31) == 0) red[tid >> 5] = v;
    __syncthreads();
    if (tid == 0) {
        float s = 0.f;
        for (int i = 0; i < 8; i++) s += red[i];
        out[n] = s + bd2[0];
    }
}

// ---------------- launch ----------------
extern "C" void kernel_launch(void* const* d_in, const int* in_sizes, int n_in,
                              void* d_out, int out_size) {
    const float* x        = (const float*)d_in[0];
    const float* Wfc      = (const float*)d_in[3];
    const float* bfc      = (const float*)d_in[4];
    const float* cls_tok  = (const float*)d_in[5];
    const float* pos_emb  = (const float*)d_in[6];
    const float* emb1     = (const float*)d_in[7];
    const float* emb2     = (const float*)d_in[8];
    const float* Wl1      = (const float*)d_in[9];
    const float* bl1      = (const float*)d_in[10];
    const float* Wl2      = (const float*)d_in[11];
    const float* bl2      = (const float*)d_in[12];
    const float* Wqkv     = (const float*)d_in[13];
    const float* bqkv     = (const float*)d_in[14];
    const float* Wo       = (const float*)d_in[15];
    const float* bo       = (const float*)d_in[16];
    const float* W1       = (const float*)d_in[17];
    const float* b1       = (const float*)d_in[18];
    const float* W2       = (const float*)d_in[19];
    const float* b2       = (const float*)d_in[20];
    const float* ln1g     = (const float*)d_in[21];
    const float* ln1b     = (const float*)d_in[22];
    const float* ln2g     = (const float*)d_in[23];
    const float* ln2b     = (const float*)d_in[24];
    const float* Wmlp     = (const float*)d_in[25];
    const float* bmlp     = (const float*)d_in[26];
    const float* Wd1      = (const float*)d_in[27];
    const float* bd1      = (const float*)d_in[28];
    const float* Wd2      = (const float*)d_in[29];
    const float* bd2      = (const float*)d_in[30];
    float* out = (float*)d_out;

    float *p_h, *p_qkv, *p_attn, *p_tmp, *p_a, *p_X, *p_H1, *p_H2, *p_d1;
    cudaGetSymbolAddress((void**)&p_h,    d_h);
    cudaGetSymbolAddress((void**)&p_qkv,  d_qkv);
    cudaGetSymbolAddress((void**)&p_attn, d_attn);
    cudaGetSymbolAddress((void**)&p_tmp,  d_tmp);
    cudaGetSymbolAddress((void**)&p_a,    d_a);
    cudaGetSymbolAddress((void**)&p_X,    d_X);
    cudaGetSymbolAddress((void**)&p_H1,   d_H1);
    cudaGetSymbolAddress((void**)&p_H2,   d_H2);
    cudaGetSymbolAddress((void**)&p_d1,   d_d1);

    // embedding + graph
    k_embed<<<M_ROWS, 256>>>(x, Wfc, bfc, cls_tok, pos_emb, p_h);
    k_graph<<<1, 256>>>(emb1, emb2, Wl1, bl1, Wl2, bl2, p_a);

    for (int l = 0; l < LAYERS; l++) {
        if (l > 0) {
            k_extract<<<4096, 256>>>(p_h, p_X);
            k_prop<<<4096, 256>>>(p_a, p_X,  p_H1);
            k_prop<<<4096, 256>>>(p_a, p_H1, p_H2);
            k_mixout<<<4096, 256>>>(p_X, p_H1, p_H2,
                                    Wmlp + (size_t)(l-1)*256*768, bmlp + (l-1)*256, p_h);
        }
        // QKV
        k_gemm<<<dim3(768/128, M_ROWS/128), 256>>>(p_h, Wqkv + (size_t)l*768*256,
                                                   bqkv + l*768, p_qkv,
                                                   M_ROWS, 768, 256, 0);
        // attention
        k_attn<<<dim3(NH, SEQS), 128>>>(p_qkv, p_attn);
        // O-proj -> tmp
        k_gemm<<<dim3(256/128, M_ROWS/128), 256>>>(p_attn, Wo + (size_t)l*256*256,
                                                   bo + l*256, p_tmp,
                                                   M_ROWS, 256, 256, 0);
        k_addln<<<M_ROWS, 256>>>(p_h, p_tmp, ln1g + l*256, ln1b + l*256);
        // FF1 (relu) -> tmp
        k_gemm<<<dim3(1024/128, M_ROWS/128), 256>>>(p_h, W1 + (size_t)l*1024*256,
                                                    b1 + l*1024, p_tmp,
                                                    M_ROWS, 1024, 256, 1);
        // FF2 -> attn buffer
        k_gemm<<<dim3(256/128, M_ROWS/128), 256>>>(p_tmp, W2 + (size_t)l*256*1024,
                                                   b2 + l*256, p_attn,
                                                   M_ROWS, 256, 1024, 0);
        k_addln<<<M_ROWS, 256>>>(p_h, p_attn, ln2g + l*256, ln2b + l*256);
    }

    // decoder
    k_dec1<<<BS, 256>>>(p_h, Wd1, bd1, p_d1);
    k_dec2<<<BS, 256>>>(p_d1, Wd2, bd2, out);
}

// round 6
// speedup vs baseline: 1.3457x; 1.3457x over previous
#include <cuda_runtime.h>
#include <cuda_bf16.h>
#include <math.h>
#include <stdint.h>

// ---------------- model dims ----------------
#define BS   64
#define T    96
#define C    16
#define INF_ 16
#define H    256
#define NH   8
#define DH   32
#define NCLS 4
#define L    100           // T + NCLS
#define LAYERS 4
#define M_ROWS (1024*100)  // (BS*C) * L = 102400
#define SEQS   1024        // BS*C

// ---------------- fp32 scratch ----------------
__device__ float d_h   [26214400];   // (1024,100,256)
__device__ float d_qkv [78643200];   // (1024,100,768)
__device__ float d_o   [26214400];   // gemm fp32 outputs (O-proj / FF2)
__device__ float d_a   [256];
__device__ float d_X   [1048576];
__device__ float d_H1  [1048576];
__device__ float d_H2  [1048576];
__device__ float d_d1  [16384];

// ---------------- bf16 hi/lo scratch ----------------
__device__ __nv_bfloat16 g_hhi[26214400],  g_hlo[26214400];    // h (enc input)
__device__ __nv_bfloat16 g_ahi[26214400],  g_alo[26214400];    // attn output
__device__ __nv_bfloat16 g_thi[104857600], g_tlo[104857600];   // FF1 output
__device__ __nv_bfloat16 g_wqkvh[786432],  g_wqkvl[786432];
__device__ __nv_bfloat16 g_woh[262144],    g_wol[262144];
__device__ __nv_bfloat16 g_w1h[1048576],   g_w1l[1048576];
__device__ __nv_bfloat16 g_w2h[1048576],   g_w2l[1048576];

// ---------------- asm helpers (base sm_103 target: ldmatrix/mma.sync/cp.async) ----
__device__ __forceinline__ uint32_t smem_u32(const void* p) {
    uint32_t a;
    asm("{ .reg .u64 t; cvta.to.shared.u64 t, %1; cvt.u32.u64 %0, t; }" : "=r"(a) : "l"(p));
    return a;
}
#define CP16(s, g) asm volatile("cp.async.cg.shared.global [%0], [%1], 16;" :: "r"(s), "l"(g))
#define CP_COMMIT() asm volatile("cp.async.commit_group;")
#define CP_WAIT0()  asm volatile("cp.async.wait_group 0;" ::: "memory")
#define LDSM_X4(r0,r1,r2,r3,addr) \
    asm volatile("ldmatrix.sync.aligned.m8n8.x4.shared.b16 {%0,%1,%2,%3}, [%4];" \
        : "=r"(r0),"=r"(r1),"=r"(r2),"=r"(r3) : "r"(addr))
#define LDSM_X2(r0,r1,addr) \
    asm volatile("ldmatrix.sync.aligned.m8n8.x2.shared.b16 {%0,%1}, [%2];" \
        : "=r"(r0),"=r"(r1) : "r"(addr))
#define MMA16816(c0,c1,c2,c3,a0,a1,a2,a3,b0,b1) \
    asm volatile("mma.sync.aligned.m16n8k16.row.col.f32.bf16.bf16.f32 " \
        "{%0,%1,%2,%3},{%4,%5,%6,%7},{%8,%9},{%0,%1,%2,%3};" \
        : "+f"(c0),"+f"(c1),"+f"(c2),"+f"(c3) \
        : "r"(a0),"r"(a1),"r"(a2),"r"(a3),"r"(b0),"r"(b1))

__device__ __forceinline__ void split_hilo(float v, __nv_bfloat16& h, __nv_bfloat16& lo) {
    h = __float2bfloat16(v);
    lo = __float2bfloat16(v - __bfloat162float(h));
}

// ============================================================================
// bf16 split GEMM: C(MxN) = Ahi@Bhi^T + Alo@Bhi^T + Ahi@Blo^T (+bias, relu?)
// A,B given as bf16 hi/lo (row-major MxK / NxK). CTA 128x128, BK=64, 8 warps.
// smem tiles padded to stride 72 bf16 for conflict-free ldmatrix.
// ============================================================================
#define TSTRIDE 72
#define TILE_B  (128*TSTRIDE*2)      // 18432 bytes per tile
#define GSMEM   (4*TILE_B)           // 73728

__global__ __launch_bounds__(256) void k_gemm_mma(
    const __nv_bfloat16* __restrict__ Ahi, const __nv_bfloat16* __restrict__ Alo,
    const __nv_bfloat16* __restrict__ Bhi, const __nv_bfloat16* __restrict__ Blo,
    const float* __restrict__ bias,
    float* __restrict__ Cf32, __nv_bfloat16* __restrict__ Chi, __nv_bfloat16* __restrict__ Clo,
    int M, int N, int K, int relu) {
    extern __shared__ __align__(128) char smem[];
    uint32_t sb = smem_u32(smem);
    const uint32_t sA_hi = sb, sA_lo = sb + TILE_B, sB_hi = sb + 2*TILE_B, sB_lo = sb + 3*TILE_B;

    const int tid = threadIdx.x, lane = tid & 31, wid = tid >> 5;
    const int wm = wid >> 2, wn = wid & 3;          // 2 x 4 warp grid
    const int m0 = blockIdx.y * 128, n0 = blockIdx.x * 128;

    float acc[4][4][4];
#pragma unroll
    for (int a = 0; a < 4; a++)
#pragma unroll
        for (int b = 0; b < 4; b++)
#pragma unroll
            for (int c = 0; c < 4; c++) acc[a][b][c] = 0.f;

    // ldmatrix relative offsets (bytes within a tile)
    const int l2 = lane & 15;
    const uint32_t a_rel_row = (uint32_t)((lane & 7) + ((lane >> 3) & 1) * 8);
    const uint32_t a_rel_col = (uint32_t)((lane >> 4) * 8);
    const uint32_t b_rel_row = (uint32_t)(l2 & 7);
    const uint32_t b_rel_col = (uint32_t)(((l2 >> 3) & 1) * 8);

    for (int k0 = 0; k0 < K; k0 += 64) {
        // ---- stage 4 tiles (128x64 bf16 each) via cp.async ----
#pragma unroll
        for (int i = 0; i < 4; i++) {
            int idx = tid + i * 256;          // 0..1023
            int r = idx >> 3, c8 = idx & 7;
            uint32_t soff = (uint32_t)(r * TSTRIDE + c8 * 8) * 2;
            size_t ga = (size_t)(m0 + r) * K + k0 + c8 * 8;
            size_t gb = (size_t)(n0 + r) * K + k0 + c8 * 8;
            CP16(sA_hi + soff, Ahi + ga);
            CP16(sA_lo + soff, Alo + ga);
            CP16(sB_hi + soff, Bhi + gb);
            CP16(sB_lo + soff, Blo + gb);
        }
        CP_COMMIT();
        CP_WAIT0();
        __syncthreads();

        // ---- compute: 4 k-steps of 16 ----
#pragma unroll
        for (int kk = 0; kk < 4; kk++) {
            uint32_t bh[4][2], bl[4][2];
#pragma unroll
            for (int nt = 0; nt < 4; nt++) {
                uint32_t rel = ((uint32_t)((wn*32 + nt*8 + b_rel_row) * TSTRIDE)
                                + kk*16 + b_rel_col) * 2;
                LDSM_X2(bh[nt][0], bh[nt][1], sB_hi + rel);
                LDSM_X2(bl[nt][0], bl[nt][1], sB_lo + rel);
            }
#pragma unroll
            for (int mt = 0; mt < 4; mt++) {
                uint32_t rel = ((uint32_t)((wm*64 + mt*16 + a_rel_row) * TSTRIDE)
                                + kk*16 + a_rel_col) * 2;
                uint32_t ah[4], al[4];
                LDSM_X4(ah[0], ah[1], ah[2], ah[3], sA_hi + rel);
                LDSM_X4(al[0], al[1], al[2], al[3], sA_lo + rel);
#pragma unroll
                for (int nt = 0; nt < 4; nt++) {
                    MMA16816(acc[mt][nt][0], acc[mt][nt][1], acc[mt][nt][2], acc[mt][nt][3],
                             ah[0], ah[1], ah[2], ah[3], bh[nt][0], bh[nt][1]);
                    MMA16816(acc[mt][nt][0], acc[mt][nt][1], acc[mt][nt][2], acc[mt][nt][3],
                             al[0], al[1], al[2], al[3], bh[nt][0], bh[nt][1]);
                    MMA16816(acc[mt][nt][0], acc[mt][nt][1], acc[mt][nt][2], acc[mt][nt][3],
                             ah[0], ah[1], ah[2], ah[3], bl[nt][0], bl[nt][1]);
                }
            }
        }
        __syncthreads();
    }

    // ---- epilogue ----
#pragma unroll
    for (int mt = 0; mt < 4; mt++) {
#pragma unroll
        for (int nt = 0; nt < 4; nt++) {
            int row = m0 + wm*64 + mt*16 + (lane >> 2);
            int col = n0 + wn*32 + nt*8 + (lane & 3)*2;
            float b0 = bias[col], b1 = bias[col + 1];
            float v00 = acc[mt][nt][0] + b0, v01 = acc[mt][nt][1] + b1;
            float v10 = acc[mt][nt][2] + b0, v11 = acc[mt][nt][3] + b1;
            if (relu) {
                v00 = fmaxf(v00, 0.f); v01 = fmaxf(v01, 0.f);
                v10 = fmaxf(v10, 0.f); v11 = fmaxf(v11, 0.f);
            }
            if (Cf32) {
                *reinterpret_cast<float2*>(Cf32 + (size_t)row*N + col)     = make_float2(v00, v01);
                *reinterpret_cast<float2*>(Cf32 + (size_t)(row+8)*N + col) = make_float2(v10, v11);
            }
            if (Chi) {
                __nv_bfloat16 h00, l00, h01, l01, h10, l10, h11, l11;
                split_hilo(v00, h00, l00); split_hilo(v01, h01, l01);
                split_hilo(v10, h10, l10); split_hilo(v11, h11, l11);
                *reinterpret_cast<__nv_bfloat162*>(Chi + (size_t)row*N + col)     = __nv_bfloat162(h00, h01);
                *reinterpret_cast<__nv_bfloat162*>(Clo + (size_t)row*N + col)     = __nv_bfloat162(l00, l01);
                *reinterpret_cast<__nv_bfloat162*>(Chi + (size_t)(row+8)*N + col) = __nv_bfloat162(h10, h11);
                *reinterpret_cast<__nv_bfloat162*>(Clo + (size_t)(row+8)*N + col) = __nv_bfloat162(l10, l11);
            }
        }
    }
}

// ---------------- weight fp32 -> hi/lo bf16 ----------------
__global__ void k_cvt(const float* __restrict__ in, __nv_bfloat16* __restrict__ hi,
                      __nv_bfloat16* __restrict__ lo, int n) {
    int i = blockIdx.x*256 + threadIdx.x;
    if (i < n) {
        __nv_bfloat16 h, l;
        split_hilo(in[i], h, l);
        hi[i] = h; lo[i] = l;
    }
}

// ---------------- embedding (writes fp32 h + hi/lo) ----------------
__global__ void k_embed(const float* __restrict__ x, const float* __restrict__ Wfc,
                        const float* __restrict__ bfc, const float* __restrict__ cls,
                        const float* __restrict__ pos, float* __restrict__ hout,
                        __nv_bfloat16* __restrict__ hhi, __nv_bfloat16* __restrict__ hlo) {
    int r = blockIdx.x;
    int s = r / L, l = r % L;
    int b = s >> 4, c = s & 15;
    int o = threadIdx.x;
    float v;
    if (l < T) {
        const float* xr = x + (((size_t)(b*T + l))*C + c)*INF_;
        const float* wr = Wfc + o*INF_;
        float acc = bfc[o];
#pragma unroll
        for (int i = 0; i < INF_; i++) acc += xr[i]*wr[i];
        v = acc;
    } else {
        v = cls[((l - T)*C + c)*H + o];
    }
    v += pos[(l*C + c)*H + o];
    size_t idx = (size_t)r*H + o;
    hout[idx] = v;
    __nv_bfloat16 hh, ll; split_hilo(v, hh, ll);
    hhi[idx] = hh; hlo[idx] = ll;
}

// ---------------- graph constructor ----------------
__global__ void k_graph(const float* __restrict__ emb1, const float* __restrict__ emb2,
                        const float* __restrict__ Wl1, const float* __restrict__ bl1,
                        const float* __restrict__ Wl2, const float* __restrict__ bl2,
                        float* __restrict__ a_out) {
    __shared__ float sm1[16][256];
    __shared__ float sm2[16][256];
    int o = threadIdx.x;
    for (int c = 0; c < 16; c++) {
        float s1 = bl1[o], s2 = bl2[o];
        const float* e1 = emb1 + c*256;
        const float* e2 = emb2 + c*256;
        const float* w1 = Wl1 + o*256;
        const float* w2 = Wl2 + o*256;
        for (int i = 0; i < 256; i++) { s1 += e1[i]*w1[i]; s2 += e2[i]*w2[i]; }
        sm1[c][o] = tanhf(s1); sm2[c][o] = tanhf(s2);
    }
    __syncthreads();
    int v = o >> 4, w = o & 15;
    float s = 0.f;
    for (int k = 0; k < 256; k++) s += sm1[v][k]*sm2[w][k] - sm2[v][k]*sm1[w][k];
    float adj = fmaxf(tanhf(s), 0.f) + ((v == w) ? 1.f : 0.f);
    __shared__ float sadj[256];
    __shared__ float srow[16];
    sadj[o] = adj;
    __syncthreads();
    if (o < 16) {
        float rs = 0.f;
        for (int j = 0; j < 16; j++) rs += sadj[o*16 + j];
        srow[o] = rs;
    }
    __syncthreads();
    a_out[o] = sadj[o] / srow[v];
}

// ---------------- fused attention (writes hi/lo output) ----------------
__global__ void k_attn(const float* __restrict__ qkv,
                       __nv_bfloat16* __restrict__ ohi, __nv_bfloat16* __restrict__ olo) {
    int hh = blockIdx.x;
    int s  = blockIdx.y;
    int tid = threadIdx.x;
    __shared__ float Ks[100][32];
    __shared__ float Vs[100][32];
    const float* base = qkv + (size_t)s*L*768;
    for (int idx = tid; idx < L*DH; idx += 128) {
        int l = idx >> 5, d = idx & 31;
        Ks[l][d] = base[l*768 + 256 + hh*DH + d];
        Vs[l][d] = base[l*768 + 512 + hh*DH + d];
    }
    __syncthreads();
    if (tid < L) {
        int lq = tid;
        float q[DH];
        const float* qp = base + lq*768 + hh*DH;
#pragma unroll
        for (int d = 0; d < DH; d++) q[d] = qp[d] * 0.17677669529663687f;
        int kmax = (lq >= T) ? L : (lq + 1);
        float m = -1e30f, sum = 0.f;
        float acc[DH];
#pragma unroll
        for (int d = 0; d < DH; d++) acc[d] = 0.f;
        for (int k = 0; k < kmax; k++) {
            float sc = 0.f;
#pragma unroll
            for (int d = 0; d < DH; d++) sc += q[d]*Ks[k][d];
            float mn = fmaxf(m, sc);
            float corr = expf(m - mn);
            float pr   = expf(sc - mn);
            sum = sum*corr + pr;
#pragma unroll
            for (int d = 0; d < DH; d++) acc[d] = acc[d]*corr + pr*Vs[k][d];
            m = mn;
        }
        float inv = 1.f/sum;
        size_t off = ((size_t)s*L + lq)*H + hh*DH;
#pragma unroll
        for (int d = 0; d < DH; d++) {
            __nv_bfloat16 hh2, ll; split_hilo(acc[d]*inv, hh2, ll);
            ohi[off + d] = hh2; olo[off + d] = ll;
        }
    }
}

// ---------------- residual add + LayerNorm (writes fp32 + hi/lo) ----------------
__global__ void k_addln(float* __restrict__ h, const float* __restrict__ p,
                        const float* __restrict__ g, const float* __restrict__ b,
                        __nv_bfloat16* __restrict__ hhi, __nv_bfloat16* __restrict__ hlo) {
    int r = blockIdx.x, o = threadIdx.x;
    size_t idx = (size_t)r*H + o;
    float v = h[idx] + p[idx];
    __shared__ float red[8];
    float s = v;
#pragma unroll
    for (int off = 16; off > 0; off >>= 1) s += __shfl_down_sync(0xffffffffu, s, off);
    int lane = o & 31, wid = o >> 5;
    if (lane == 0) red[wid] = s;
    __syncthreads();
    if (o == 0) {
        float t = 0.f;
        for (int i = 0; i < 8; i++) t += red[i];
        red[0] = t * (1.f/H);
    }
    __syncthreads();
    float mean = red[0];
    __syncthreads();
    float d = v - mean;
    s = d*d;
#pragma unroll
    for (int off = 16; off > 0; off >>= 1) s += __shfl_down_sync(0xffffffffu, s, off);
    if (lane == 0) red[wid] = s;
    __syncthreads();
    if (o == 0) {
        float t = 0.f;
        for (int i = 0; i < 8; i++) t += red[i];
        red[0] = rsqrtf(t * (1.f/H) + 1e-5f);
    }
    __syncthreads();
    float rstd = red[0];
    float outv = d*rstd*g[o] + b[o];
    h[idx] = outv;
    __nv_bfloat16 hh, ll; split_hilo(outv, hh, ll);
    hhi[idx] = hh; hlo[idx] = ll;
}

// ---------------- mixprop pieces ----------------
__global__ void k_extract(const float* __restrict__ h, float* __restrict__ X) {
    int b = blockIdx.x;
    int ch = threadIdx.x;
    int lc = b & 3, sw = b >> 2;
    X[(size_t)b*H + ch] = h[(size_t)sw*(L*H) + (T + lc)*H + ch];
}

__global__ void k_prop(const float* __restrict__ a, const float* __restrict__ in,
                       float* __restrict__ out) {
    __shared__ float sa[256];
    int tid = threadIdx.x;
    sa[tid] = a[tid];
    __syncthreads();
    int b = blockIdx.x;
    int lc = b & 3, v = (b >> 2) & 15, n = b >> 6;
    float acc = 0.f;
#pragma unroll
    for (int w = 0; w < 16; w++)
        acc += sa[v*16 + w] * in[((size_t)(n*16 + w)*4 + lc)*H + tid];
    out[(size_t)b*H + tid] = acc;
}

__global__ void k_mixout(const float* __restrict__ X, const float* __restrict__ H1,
                         const float* __restrict__ H2, const float* __restrict__ Wm,
                         const float* __restrict__ bm, float* __restrict__ h,
                         __nv_bfloat16* __restrict__ hhi, __nv_bfloat16* __restrict__ hlo) {
    __shared__ float row[768];
    int b = blockIdx.x, o = threadIdx.x;
    row[o]       = X [(size_t)b*H + o];
    row[256 + o] = H1[(size_t)b*H + o];
    row[512 + o] = H2[(size_t)b*H + o];
    __syncthreads();
    const float* wr = Wm + (size_t)o*768;
    float acc = bm[o];
    for (int ch = 0; ch < 768; ch++) acc += wr[ch]*row[ch];
    int lc = b & 3, sw = b >> 2;
    size_t idx = (size_t)sw*(L*H) + (T + lc)*H + o;
    h[idx] = acc;
    __nv_bfloat16 hh, ll; split_hilo(acc, hh, ll);
    hhi[idx] = hh; hlo[idx] = ll;
}

// ---------------- decoder ----------------
__global__ void k_dec1(const float* __restrict__ h, const float* __restrict__ Wd1,
                       const float* __restrict__ bd1, float* __restrict__ d1) {
    __shared__ float zc[1024];
    int n = blockIdx.x, o = threadIdx.x;
    float acc = 0.f;
    for (int c = 0; c < 16; c++) {
        const float* hp = h + (size_t)(n*16 + c)*(L*H) + T*H;
        for (int jj = o; jj < 1024; jj += 256) zc[jj] = tanhf(hp[jj]);
        __syncthreads();
        const float* wr = Wd1 + (size_t)o*16384 + c*1024;
        float a = 0.f;
        for (int jj = 0; jj < 1024; jj++) a += wr[jj]*zc[jj];
        acc += a;
        __syncthreads();
    }
    acc += bd1[o];
    d1[n*H + o] = 0.5f*acc*(1.f + erff(acc*0.70710678118654752f));
}

__global__ void k_dec2(const float* __restrict__ d1, const float* __restrict__ Wd2,
                       const float* __restrict__ bd2, float* __restrict__ out) {
    int n = blockIdx.x, tid = threadIdx.x;
    float v = d1[n*H + tid]*Wd2[tid];
    __shared__ float red[8];
#pragma unroll
    for (int off = 16; off > 0; off >>= 1) v += __shfl_down_sync(0xffffffffu, v, off);
    if ((tid & 31) == 0) red[tid >> 5] = v;
    __syncthreads();
    if (tid == 0) {
        float s = 0.f;
        for (int i = 0; i < 8; i++) s += red[i];
        out[n] = s + bd2[0];
    }
}

// ---------------- launch ----------------
extern "C" void kernel_launch(void* const* d_in, const int* in_sizes, int n_in,
                              void* d_out, int out_size) {
    const float* x        = (const float*)d_in[0];
    const float* Wfc      = (const float*)d_in[3];
    const float* bfc      = (const float*)d_in[4];
    const float* cls_tok  = (const float*)d_in[5];
    const float* pos_emb  = (const float*)d_in[6];
    const float* emb1     = (const float*)d_in[7];
    const float* emb2     = (const float*)d_in[8];
    const float* Wl1      = (const float*)d_in[9];
    const float* bl1      = (const float*)d_in[10];
    const float* Wl2      = (const float*)d_in[11];
    const float* bl2      = (const float*)d_in[12];
    const float* Wqkv     = (const float*)d_in[13];
    const float* bqkv     = (const float*)d_in[14];
    const float* Wo       = (const float*)d_in[15];
    const float* bo       = (const float*)d_in[16];
    const float* W1       = (const float*)d_in[17];
    const float* b1       = (const float*)d_in[18];
    const float* W2       = (const float*)d_in[19];
    const float* b2       = (const float*)d_in[20];
    const float* ln1g     = (const float*)d_in[21];
    const float* ln1b     = (const float*)d_in[22];
    const float* ln2g     = (const float*)d_in[23];
    const float* ln2b     = (const float*)d_in[24];
    const float* Wmlp     = (const float*)d_in[25];
    const float* bmlp     = (const float*)d_in[26];
    const float* Wd1      = (const float*)d_in[27];
    const float* bd1      = (const float*)d_in[28];
    const float* Wd2      = (const float*)d_in[29];
    const float* bd2      = (const float*)d_in[30];
    float* out = (float*)d_out;

    float *p_h, *p_qkv, *p_o, *p_a, *p_X, *p_H1, *p_H2, *p_d1;
    __nv_bfloat16 *p_hhi, *p_hlo, *p_ahi, *p_alo, *p_thi, *p_tlo;
    __nv_bfloat16 *p_wqkvh, *p_wqkvl, *p_woh, *p_wol, *p_w1h, *p_w1l, *p_w2h, *p_w2l;
    cudaGetSymbolAddress((void**)&p_h,    d_h);
    cudaGetSymbolAddress((void**)&p_qkv,  d_qkv);
    cudaGetSymbolAddress((void**)&p_o,    d_o);
    cudaGetSymbolAddress((void**)&p_a,    d_a);
    cudaGetSymbolAddress((void**)&p_X,    d_X);
    cudaGetSymbolAddress((void**)&p_H1,   d_H1);
    cudaGetSymbolAddress((void**)&p_H2,   d_H2);
    cudaGetSymbolAddress((void**)&p_d1,   d_d1);
    cudaGetSymbolAddress((void**)&p_hhi,  g_hhi);  cudaGetSymbolAddress((void**)&p_hlo, g_hlo);
    cudaGetSymbolAddress((void**)&p_ahi,  g_ahi);  cudaGetSymbolAddress((void**)&p_alo, g_alo);
    cudaGetSymbolAddress((void**)&p_thi,  g_thi);  cudaGetSymbolAddress((void**)&p_tlo, g_tlo);
    cudaGetSymbolAddress((void**)&p_wqkvh, g_wqkvh); cudaGetSymbolAddress((void**)&p_wqkvl, g_wqkvl);
    cudaGetSymbolAddress((void**)&p_woh,   g_woh);   cudaGetSymbolAddress((void**)&p_wol,   g_wol);
    cudaGetSymbolAddress((void**)&p_w1h,   g_w1h);   cudaGetSymbolAddress((void**)&p_w1l,   g_w1l);
    cudaGetSymbolAddress((void**)&p_w2h,   g_w2h);   cudaGetSymbolAddress((void**)&p_w2l,   g_w2l);

    cudaFuncSetAttribute(k_gemm_mma, cudaFuncAttributeMaxDynamicSharedMemorySize, GSMEM);

    // weight conversion (all layers at once)
    k_cvt<<<(786432 + 255)/256, 256>>>(Wqkv, p_wqkvh, p_wqkvl, 786432);
    k_cvt<<<(262144 + 255)/256, 256>>>(Wo,   p_woh,   p_wol,   262144);
    k_cvt<<<(1048576 + 255)/256, 256>>>(W1,  p_w1h,   p_w1l,   1048576);
    k_cvt<<<(1048576 + 255)/256, 256>>>(W2,  p_w2h,   p_w2l,   1048576);

    // embedding + graph
    k_embed<<<M_ROWS, 256>>>(x, Wfc, bfc, cls_tok, pos_emb, p_h, p_hhi, p_hlo);
    k_graph<<<1, 256>>>(emb1, emb2, Wl1, bl1, Wl2, bl2, p_a);

    for (int l = 0; l < LAYERS; l++) {
        if (l > 0) {
            k_extract<<<4096, 256>>>(p_h, p_X);
            k_prop<<<4096, 256>>>(p_a, p_X,  p_H1);
            k_prop<<<4096, 256>>>(p_a, p_H1, p_H2);
            k_mixout<<<4096, 256>>>(p_X, p_H1, p_H2,
                                    Wmlp + (size_t)(l-1)*256*768, bmlp + (l-1)*256,
                                    p_h, p_hhi, p_hlo);
        }
        // QKV: (M_ROWS x 256) @ (768 x 256)^T -> fp32 qkv
        k_gemm_mma<<<dim3(768/128, M_ROWS/128), 256, GSMEM>>>(
            p_hhi, p_hlo, p_wqkvh + (size_t)l*768*256, p_wqkvl + (size_t)l*768*256,
            bqkv + l*768, p_qkv, nullptr, nullptr, M_ROWS, 768, 256, 0);
        // attention -> hi/lo
        k_attn<<<dim3(NH, SEQS), 128>>>(p_qkv, p_ahi, p_alo);
        // O-proj -> fp32 d_o
        k_gemm_mma<<<dim3(256/128, M_ROWS/128), 256, GSMEM>>>(
            p_ahi, p_alo, p_woh + (size_t)l*256*256, p_wol + (size_t)l*256*256,
            bo + l*256, p_o, nullptr, nullptr, M_ROWS, 256, 256, 0);
        k_addln<<<M_ROWS, 256>>>(p_h, p_o, ln1g + l*256, ln1b + l*256, p_hhi, p_hlo);
        // FF1 (relu) -> hi/lo tmp
        k_gemm_mma<<<dim3(1024/128, M_ROWS/128), 256, GSMEM>>>(
            p_hhi, p_hlo, p_w1h + (size_t)l*1024*256, p_w1l + (size_t)l*1024*256,
            b1 + l*1024, nullptr, p_thi, p_tlo, M_ROWS, 1024, 256, 1);
        // FF2 -> fp32 d_o
        k_gemm_mma<<<dim3(256/128, M_ROWS/128), 256, GSMEM>>>(
            p_thi, p_tlo, p_w2h + (size_t)l*256*1024, p_w2l + (size_t)l*256*1024,
            b2 + l*256, p_o, nullptr, nullptr, M_ROWS, 256, 1024, 0);
        k_addln<<<M_ROWS, 256>>>(p_h, p_o, ln2g + l*256, ln2b + l*256, p_hhi, p_hlo);
    }

    // decoder
    k_dec1<<<BS, 256>>>(p_h, Wd1, bd1, p_d1);
    k_dec2<<<BS, 256>>>(p_d1, Wd2, bd2, out);
}

// round 7
// speedup vs baseline: 1.4152x; 1.0516x over previous
#include <cuda_runtime.h>
#include <cuda_bf16.h>
#include <math.h>
#include <stdint.h>

// ---------------- model dims ----------------
#define BS   64
#define T    96
#define C    16
#define INF_ 16
#define H    256
#define NH   8
#define DH   32
#define NCLS 4
#define L    100           // T + NCLS
#define LAYERS 4
#define M_ROWS (1024*100)  // (BS*C) * L = 102400
#define SEQS   1024        // BS*C

// ---------------- fp32 scratch ----------------
__device__ float d_h   [26214400];   // (1024,100,256)
__device__ float d_qkv [78643200];   // (1024,100,768)
__device__ float d_o   [26214400];   // gemm fp32 outputs (O-proj / FF2)
__device__ float d_a   [256];
__device__ float d_X   [1048576];
__device__ float d_H1  [1048576];
__device__ float d_H2  [1048576];
__device__ float d_d1  [16384];

// ---------------- bf16 hi/lo scratch ----------------
__device__ __nv_bfloat16 g_hhi[26214400],  g_hlo[26214400];    // h (enc input)
__device__ __nv_bfloat16 g_ahi[26214400],  g_alo[26214400];    // attn output
__device__ __nv_bfloat16 g_thi[104857600], g_tlo[104857600];   // FF1 output
__device__ __nv_bfloat16 g_wqkvh[786432],  g_wqkvl[786432];
__device__ __nv_bfloat16 g_woh[262144],    g_wol[262144];
__device__ __nv_bfloat16 g_w1h[1048576],   g_w1l[1048576];
__device__ __nv_bfloat16 g_w2h[1048576],   g_w2l[1048576];

// ---------------- asm helpers ----------------
__device__ __forceinline__ uint32_t smem_u32(const void* p) {
    uint32_t a;
    asm("{ .reg .u64 t; cvta.to.shared.u64 t, %1; cvt.u32.u64 %0, t; }" : "=r"(a) : "l"(p));
    return a;
}
#define CP16(s, g) asm volatile("cp.async.cg.shared.global [%0], [%1], 16;" :: "r"(s), "l"(g))
#define CP_COMMIT() asm volatile("cp.async.commit_group;")
#define CP_WAIT(n)  asm volatile("cp.async.wait_group %0;" :: "n"(n) : "memory")
#define LDSM_X4(r0,r1,r2,r3,addr) \
    asm volatile("ldmatrix.sync.aligned.m8n8.x4.shared.b16 {%0,%1,%2,%3}, [%4];" \
        : "=r"(r0),"=r"(r1),"=r"(r2),"=r"(r3) : "r"(addr))
#define LDSM_X2(r0,r1,addr) \
    asm volatile("ldmatrix.sync.aligned.m8n8.x2.shared.b16 {%0,%1}, [%2];" \
        : "=r"(r0),"=r"(r1) : "r"(addr))
#define MMA16816(c0,c1,c2,c3,a0,a1,a2,a3,b0,b1) \
    asm volatile("mma.sync.aligned.m16n8k16.row.col.f32.bf16.bf16.f32 " \
        "{%0,%1,%2,%3},{%4,%5,%6,%7},{%8,%9},{%0,%1,%2,%3};" \
        : "+f"(c0),"+f"(c1),"+f"(c2),"+f"(c3) \
        : "r"(a0),"r"(a1),"r"(a2),"r"(a3),"r"(b0),"r"(b1))

__device__ __forceinline__ void split_hilo(float v, __nv_bfloat16& h, __nv_bfloat16& lo) {
    h = __float2bfloat16(v);
    lo = __float2bfloat16(v - __bfloat162float(h));
}

// ============================================================================
// bf16 split GEMM, 2-stage cp.async pipeline.
// C(MxN) = Ahi@Bhi^T + Alo@Bhi^T + Ahi@Blo^T (+bias, relu?)
// CTA 128x128, BK=64, 8 warps (2x4), warp tile 64x32.
// smem: 2 stages x 4 tiles (Ahi,Alo,Bhi,Blo), stride 72 bf16 (conflict-free ldsm).
// ============================================================================
#define TSTRIDE 72
#define TILE_B  (128*TSTRIDE*2)      // 18432 bytes per tile
#define STAGE_B (4*TILE_B)           // 73728 per stage
#define GSMEM   (2*STAGE_B)          // 147456

__global__ __launch_bounds__(256) void k_gemm_mma(
    const __nv_bfloat16* __restrict__ Ahi, const __nv_bfloat16* __restrict__ Alo,
    const __nv_bfloat16* __restrict__ Bhi, const __nv_bfloat16* __restrict__ Blo,
    const float* __restrict__ bias,
    float* __restrict__ Cf32, __nv_bfloat16* __restrict__ Chi, __nv_bfloat16* __restrict__ Clo,
    int M, int N, int K, int relu) {
    extern __shared__ __align__(128) char smem[];
    uint32_t sb = smem_u32(smem);

    const int tid = threadIdx.x, lane = tid & 31, wid = tid >> 5;
    const int wm = wid >> 2, wn = wid & 3;          // 2 x 4 warp grid
    const int m0 = blockIdx.y * 128, n0 = blockIdx.x * 128;

    // per-thread staging coords: 1024 float4 slots (4 per thread)
    const int st_r  = tid >> 1;                  // 0..127 (two 8-col groups per row pair)
    float acc[4][4][4];
#pragma unroll
    for (int a = 0; a < 4; a++)
#pragma unroll
        for (int b = 0; b < 4; b++)
#pragma unroll
            for (int c = 0; c < 4; c++) acc[a][b][c] = 0.f;

    // ldmatrix relative offsets
    const int l2 = lane & 15;
    const uint32_t a_rel_row = (uint32_t)((lane & 7) + ((lane >> 3) & 1) * 8);
    const uint32_t a_rel_col = (uint32_t)((lane >> 4) * 8);
    const uint32_t b_rel_row = (uint32_t)(l2 & 7);
    const uint32_t b_rel_col = (uint32_t)(((l2 >> 3) & 1) * 8);

    const int nch = K >> 6;

    // ---- staging lambda-equivalent (macro-free helper via plain code) ----
    // each thread copies 4 x 16B per tile; layout: idx = tid + i*256 over 1024 slots
#define STAGE_CHUNK(stage, k0)                                                 \
    do {                                                                       \
        uint32_t sA_hi = sb + (stage)*STAGE_B;                                 \
        uint32_t sA_lo = sA_hi + TILE_B;                                       \
        uint32_t sB_hi = sA_hi + 2*TILE_B;                                     \
        uint32_t sB_lo = sA_hi + 3*TILE_B;                                     \
        _Pragma("unroll")                                                      \
        for (int i = 0; i < 4; i++) {                                          \
            int idx = tid + i * 256;                                           \
            int r = idx >> 3, c8 = idx & 7;                                    \
            uint32_t soff = (uint32_t)(r * TSTRIDE + c8 * 8) * 2;              \
            size_t ga = (size_t)(m0 + r) * K + (k0) + c8 * 8;                  \
            size_t gb = (size_t)(n0 + r) * K + (k0) + c8 * 8;                  \
            CP16(sA_hi + soff, Ahi + ga);                                      \
            CP16(sA_lo + soff, Alo + ga);                                      \
            CP16(sB_hi + soff, Bhi + gb);                                      \
            CP16(sB_lo + soff, Blo + gb);                                      \
        }                                                                      \
        CP_COMMIT();                                                           \
    } while (0)

    // prologue: stage chunk 0
    STAGE_CHUNK(0, 0);

    for (int ch = 0; ch < nch; ch++) {
        // prefetch next chunk into other stage
        if (ch + 1 < nch) STAGE_CHUNK((ch + 1) & 1, (ch + 1) << 6);
        // wait for current chunk (allow 1 group in flight = the prefetch)
        if (ch + 1 < nch) CP_WAIT(1); else CP_WAIT(0);
        __syncthreads();

        uint32_t sA_hi = sb + (ch & 1)*STAGE_B;
        uint32_t sA_lo = sA_hi + TILE_B;
        uint32_t sB_hi = sA_hi + 2*TILE_B;
        uint32_t sB_lo = sA_hi + 3*TILE_B;

#pragma unroll
        for (int kk = 0; kk < 4; kk++) {
            uint32_t bh[4][2], bl[4][2];
#pragma unroll
            for (int nt = 0; nt < 4; nt++) {
                uint32_t rel = ((uint32_t)((wn*32 + nt*8 + b_rel_row) * TSTRIDE)
                                + kk*16 + b_rel_col) * 2;
                LDSM_X2(bh[nt][0], bh[nt][1], sB_hi + rel);
                LDSM_X2(bl[nt][0], bl[nt][1], sB_lo + rel);
            }
#pragma unroll
            for (int mt = 0; mt < 4; mt++) {
                uint32_t rel = ((uint32_t)((wm*64 + mt*16 + a_rel_row) * TSTRIDE)
                                + kk*16 + a_rel_col) * 2;
                uint32_t ah[4], al[4];
                LDSM_X4(ah[0], ah[1], ah[2], ah[3], sA_hi + rel);
                LDSM_X4(al[0], al[1], al[2], al[3], sA_lo + rel);
#pragma unroll
                for (int nt = 0; nt < 4; nt++) {
                    MMA16816(acc[mt][nt][0], acc[mt][nt][1], acc[mt][nt][2], acc[mt][nt][3],
                             ah[0], ah[1], ah[2], ah[3], bh[nt][0], bh[nt][1]);
                    MMA16816(acc[mt][nt][0], acc[mt][nt][1], acc[mt][nt][2], acc[mt][nt][3],
                             al[0], al[1], al[2], al[3], bh[nt][0], bh[nt][1]);
                    MMA16816(acc[mt][nt][0], acc[mt][nt][1], acc[mt][nt][2], acc[mt][nt][3],
                             ah[0], ah[1], ah[2], ah[3], bl[nt][0], bl[nt][1]);
                }
            }
        }
        __syncthreads();   // all warps done with this stage before it is re-staged
    }
#undef STAGE_CHUNK

    // ---- epilogue ----
#pragma unroll
    for (int mt = 0; mt < 4; mt++) {
#pragma unroll
        for (int nt = 0; nt < 4; nt++) {
            int row = m0 + wm*64 + mt*16 + (lane >> 2);
            int col = n0 + wn*32 + nt*8 + (lane & 3)*2;
            float b0 = bias[col], b1 = bias[col + 1];
            float v00 = acc[mt][nt][0] + b0, v01 = acc[mt][nt][1] + b1;
            float v10 = acc[mt][nt][2] + b0, v11 = acc[mt][nt][3] + b1;
            if (relu) {
                v00 = fmaxf(v00, 0.f); v01 = fmaxf(v01, 0.f);
                v10 = fmaxf(v10, 0.f); v11 = fmaxf(v11, 0.f);
            }
            if (Cf32) {
                *reinterpret_cast<float2*>(Cf32 + (size_t)row*N + col)     = make_float2(v00, v01);
                *reinterpret_cast<float2*>(Cf32 + (size_t)(row+8)*N + col) = make_float2(v10, v11);
            }
            if (Chi) {
                __nv_bfloat16 h00, l00, h01, l01, h10, l10, h11, l11;
                split_hilo(v00, h00, l00); split_hilo(v01, h01, l01);
                split_hilo(v10, h10, l10); split_hilo(v11, h11, l11);
                *reinterpret_cast<__nv_bfloat162*>(Chi + (size_t)row*N + col)     = __nv_bfloat162(h00, h01);
                *reinterpret_cast<__nv_bfloat162*>(Clo + (size_t)row*N + col)     = __nv_bfloat162(l00, l01);
                *reinterpret_cast<__nv_bfloat162*>(Chi + (size_t)(row+8)*N + col) = __nv_bfloat162(h10, h11);
                *reinterpret_cast<__nv_bfloat162*>(Clo + (size_t)(row+8)*N + col) = __nv_bfloat162(l10, l11);
            }
        }
    }
}

// ---------------- weight fp32 -> hi/lo bf16 ----------------
__global__ void k_cvt(const float* __restrict__ in, __nv_bfloat16* __restrict__ hi,
                      __nv_bfloat16* __restrict__ lo, int n) {
    int i = blockIdx.x*256 + threadIdx.x;
    if (i < n) {
        __nv_bfloat16 h, l;
        split_hilo(in[i], h, l);
        hi[i] = h; lo[i] = l;
    }
}

// ---------------- embedding ----------------
__global__ void k_embed(const float* __restrict__ x, const float* __restrict__ Wfc,
                        const float* __restrict__ bfc, const float* __restrict__ cls,
                        const float* __restrict__ pos, float* __restrict__ hout,
                        __nv_bfloat16* __restrict__ hhi, __nv_bfloat16* __restrict__ hlo) {
    int r = blockIdx.x;
    int s = r / L, l = r % L;
    int b = s >> 4, c = s & 15;
    int o = threadIdx.x;
    float v;
    if (l < T) {
        const float* xr = x + (((size_t)(b*T + l))*C + c)*INF_;
        const float* wr = Wfc + o*INF_;
        float acc = bfc[o];
#pragma unroll
        for (int i = 0; i < INF_; i++) acc += xr[i]*wr[i];
        v = acc;
    } else {
        v = cls[((l - T)*C + c)*H + o];
    }
    v += pos[(l*C + c)*H + o];
    size_t idx = (size_t)r*H + o;
    hout[idx] = v;
    __nv_bfloat16 hh, ll; split_hilo(v, hh, ll);
    hhi[idx] = hh; hlo[idx] = ll;
}

// ---------------- graph constructor ----------------
__global__ void k_graph(const float* __restrict__ emb1, const float* __restrict__ emb2,
                        const float* __restrict__ Wl1, const float* __restrict__ bl1,
                        const float* __restrict__ Wl2, const float* __restrict__ bl2,
                        float* __restrict__ a_out) {
    __shared__ float sm1[16][256];
    __shared__ float sm2[16][256];
    int o = threadIdx.x;
    for (int c = 0; c < 16; c++) {
        float s1 = bl1[o], s2 = bl2[o];
        const float* e1 = emb1 + c*256;
        const float* e2 = emb2 + c*256;
        const float* w1 = Wl1 + o*256;
        const float* w2 = Wl2 + o*256;
        for (int i = 0; i < 256; i++) { s1 += e1[i]*w1[i]; s2 += e2[i]*w2[i]; }
        sm1[c][o] = tanhf(s1); sm2[c][o] = tanhf(s2);
    }
    __syncthreads();
    int v = o >> 4, w = o & 15;
    float s = 0.f;
    for (int k = 0; k < 256; k++) s += sm1[v][k]*sm2[w][k] - sm2[v][k]*sm1[w][k];
    float adj = fmaxf(tanhf(s), 0.f) + ((v == w) ? 1.f : 0.f);
    __shared__ float sadj[256];
    __shared__ float srow[16];
    sadj[o] = adj;
    __syncthreads();
    if (o < 16) {
        float rs = 0.f;
        for (int j = 0; j < 16; j++) rs += sadj[o*16 + j];
        srow[o] = rs;
    }
    __syncthreads();
    a_out[o] = sadj[o] / srow[v];
}

// ---------------- fused attention ----------------
__global__ void k_attn(const float* __restrict__ qkv,
                       __nv_bfloat16* __restrict__ ohi, __nv_bfloat16* __restrict__ olo) {
    int hh = blockIdx.x;
    int s  = blockIdx.y;
    int tid = threadIdx.x;
    __shared__ float Ks[100][32];
    __shared__ float Vs[100][32];
    const float* base = qkv + (size_t)s*L*768;
    for (int idx = tid; idx < L*DH; idx += 128) {
        int l = idx >> 5, d = idx & 31;
        Ks[l][d] = base[l*768 + 256 + hh*DH + d];
        Vs[l][d] = base[l*768 + 512 + hh*DH + d];
    }
    __syncthreads();
    if (tid < L) {
        int lq = tid;
        float q[DH];
        const float* qp = base + lq*768 + hh*DH;
#pragma unroll
        for (int d = 0; d < DH; d++) q[d] = qp[d] * 0.17677669529663687f;
        int kmax = (lq >= T) ? L : (lq + 1);
        float m = -1e30f, sum = 0.f;
        float acc[DH];
#pragma unroll
        for (int d = 0; d < DH; d++) acc[d] = 0.f;
        for (int k = 0; k < kmax; k++) {
            float sc = 0.f;
#pragma unroll
            for (int d = 0; d < DH; d++) sc += q[d]*Ks[k][d];
            float mn = fmaxf(m, sc);
            float corr = expf(m - mn);
            float pr   = expf(sc - mn);
            sum = sum*corr + pr;
#pragma unroll
            for (int d = 0; d < DH; d++) acc[d] = acc[d]*corr + pr*Vs[k][d];
            m = mn;
        }
        float inv = 1.f/sum;
        size_t off = ((size_t)s*L + lq)*H + hh*DH;
#pragma unroll
        for (int d = 0; d < DH; d++) {
            __nv_bfloat16 hh2, ll; split_hilo(acc[d]*inv, hh2, ll);
            ohi[off + d] = hh2; olo[off + d] = ll;
        }
    }
}

// ---------------- residual add + LayerNorm ----------------
__global__ void k_addln(float* __restrict__ h, const float* __restrict__ p,
                        const float* __restrict__ g, const float* __restrict__ b,
                        __nv_bfloat16* __restrict__ hhi, __nv_bfloat16* __restrict__ hlo) {
    int r = blockIdx.x, o = threadIdx.x;
    size_t idx = (size_t)r*H + o;
    float v = h[idx] + p[idx];
    __shared__ float red[8];
    float s = v;
#pragma unroll
    for (int off = 16; off > 0; off >>= 1) s += __shfl_down_sync(0xffffffffu, s, off);
    int lane = o & 31, wid = o >> 5;
    if (lane == 0) red[wid] = s;
    __syncthreads();
    if (o == 0) {
        float t = 0.f;
        for (int i = 0; i < 8; i++) t += red[i];
        red[0] = t * (1.f/H);
    }
    __syncthreads();
    float mean = red[0];
    __syncthreads();
    float d = v - mean;
    s = d*d;
#pragma unroll
    for (int off = 16; off > 0; off >>= 1) s += __shfl_down_sync(0xffffffffu, s, off);
    if (lane == 0) red[wid] = s;
    __syncthreads();
    if (o == 0) {
        float t = 0.f;
        for (int i = 0; i < 8; i++) t += red[i];
        red[0] = rsqrtf(t * (1.f/H) + 1e-5f);
    }
    __syncthreads();
    float rstd = red[0];
    float outv = d*rstd*g[o] + b[o];
    h[idx] = outv;
    __nv_bfloat16 hh, ll; split_hilo(outv, hh, ll);
    hhi[idx] = hh; hlo[idx] = ll;
}

// ---------------- mixprop pieces ----------------
__global__ void k_extract(const float* __restrict__ h, float* __restrict__ X) {
    int b = blockIdx.x;
    int ch = threadIdx.x;
    int lc = b & 3, sw = b >> 2;
    X[(size_t)b*H + ch] = h[(size_t)sw*(L*H) + (T + lc)*H + ch];
}

__global__ void k_prop(const float* __restrict__ a, const float* __restrict__ in,
                       float* __restrict__ out) {
    __shared__ float sa[256];
    int tid = threadIdx.x;
    sa[tid] = a[tid];
    __syncthreads();
    int b = blockIdx.x;
    int lc = b & 3, v = (b >> 2) & 15, n = b >> 6;
    float acc = 0.f;
#pragma unroll
    for (int w = 0; w < 16; w++)
        acc += sa[v*16 + w] * in[((size_t)(n*16 + w)*4 + lc)*H + tid];
    out[(size_t)b*H + tid] = acc;
}

__global__ void k_mixout(const float* __restrict__ X, const float* __restrict__ H1,
                         const float* __restrict__ H2, const float* __restrict__ Wm,
                         const float* __restrict__ bm, float* __restrict__ h,
                         __nv_bfloat16* __restrict__ hhi, __nv_bfloat16* __restrict__ hlo) {
    __shared__ float row[768];
    int b = blockIdx.x, o = threadIdx.x;
    row[o]       = X [(size_t)b*H + o];
    row[256 + o] = H1[(size_t)b*H + o];
    row[512 + o] = H2[(size_t)b*H + o];
    __syncthreads();
    const float* wr = Wm + (size_t)o*768;
    float acc = bm[o];
    for (int ch = 0; ch < 768; ch++) acc += wr[ch]*row[ch];
    int lc = b & 3, sw = b >> 2;
    size_t idx = (size_t)sw*(L*H) + (T + lc)*H + o;
    h[idx] = acc;
    __nv_bfloat16 hh, ll; split_hilo(acc, hh, ll);
    hhi[idx] = hh; hlo[idx] = ll;
}

// ---------------- decoder ----------------
__global__ void k_dec1(const float* __restrict__ h, const float* __restrict__ Wd1,
                       const float* __restrict__ bd1, float* __restrict__ d1) {
    __shared__ float zc[1024];
    int n = blockIdx.x, o = threadIdx.x;
    float acc = 0.f;
    for (int c = 0; c < 16; c++) {
        const float* hp = h + (size_t)(n*16 + c)*(L*H) + T*H;
        for (int jj = o; jj < 1024; jj += 256) zc[jj] = tanhf(hp[jj]);
        __syncthreads();
        const float* wr = Wd1 + (size_t)o*16384 + c*1024;
        float a = 0.f;
        for (int jj = 0; jj < 1024; jj++) a += wr[jj]*zc[jj];
        acc += a;
        __syncthreads();
    }
    acc += bd1[o];
    d1[n*H + o] = 0.5f*acc*(1.f + erff(acc*0.70710678118654752f));
}

__global__ void k_dec2(const float* __restrict__ d1, const float* __restrict__ Wd2,
                       const float* __restrict__ bd2, float* __restrict__ out) {
    int n = blockIdx.x, tid = threadIdx.x;
    float v = d1[n*H + tid]*Wd2[tid];
    __shared__ float red[8];
#pragma unroll
    for (int off = 16; off > 0; off >>= 1) v += __shfl_down_sync(0xffffffffu, v, off);
    if ((tid & 31) == 0) red[tid >> 5] = v;
    __syncthreads();
    if (tid == 0) {
        float s = 0.f;
        for (int i = 0; i < 8; i++) s += red[i];
        out[n] = s + bd2[0];
    }
}

// ---------------- launch ----------------
extern "C" void kernel_launch(void* const* d_in, const int* in_sizes, int n_in,
                              void* d_out, int out_size) {
    const float* x        = (const float*)d_in[0];
    const float* Wfc      = (const float*)d_in[3];
    const float* bfc      = (const float*)d_in[4];
    const float* cls_tok  = (const float*)d_in[5];
    const float* pos_emb  = (const float*)d_in[6];
    const float* emb1     = (const float*)d_in[7];
    const float* emb2     = (const float*)d_in[8];
    const float* Wl1      = (const float*)d_in[9];
    const float* bl1      = (const float*)d_in[10];
    const float* Wl2      = (const float*)d_in[11];
    const float* bl2      = (const float*)d_in[12];
    const float* Wqkv     = (const float*)d_in[13];
    const float* bqkv     = (const float*)d_in[14];
    const float* Wo       = (const float*)d_in[15];
    const float* bo       = (const float*)d_in[16];
    const float* W1       = (const float*)d_in[17];
    const float* b1       = (const float*)d_in[18];
    const float* W2       = (const float*)d_in[19];
    const float* b2       = (const float*)d_in[20];
    const float* ln1g     = (const float*)d_in[21];
    const float* ln1b     = (const float*)d_in[22];
    const float* ln2g     = (const float*)d_in[23];
    const float* ln2b     = (const float*)d_in[24];
    const float* Wmlp     = (const float*)d_in[25];
    const float* bmlp     = (const float*)d_in[26];
    const float* Wd1      = (const float*)d_in[27];
    const float* bd1      = (const float*)d_in[28];
    const float* Wd2      = (const float*)d_in[29];
    const float* bd2      = (const float*)d_in[30];
    float* out = (float*)d_out;

    float *p_h, *p_qkv, *p_o, *p_a, *p_X, *p_H1, *p_H2, *p_d1;
    __nv_bfloat16 *p_hhi, *p_hlo, *p_ahi, *p_alo, *p_thi, *p_tlo;
    __nv_bfloat16 *p_wqkvh, *p_wqkvl, *p_woh, *p_wol, *p_w1h, *p_w1l, *p_w2h, *p_w2l;
    cudaGetSymbolAddress((void**)&p_h,    d_h);
    cudaGetSymbolAddress((void**)&p_qkv,  d_qkv);
    cudaGetSymbolAddress((void**)&p_o,    d_o);
    cudaGetSymbolAddress((void**)&p_a,    d_a);
    cudaGetSymbolAddress((void**)&p_X,    d_X);
    cudaGetSymbolAddress((void**)&p_H1,   d_H1);
    cudaGetSymbolAddress((void**)&p_H2,   d_H2);
    cudaGetSymbolAddress((void**)&p_d1,   d_d1);
    cudaGetSymbolAddress((void**)&p_hhi,  g_hhi);  cudaGetSymbolAddress((void**)&p_hlo, g_hlo);
    cudaGetSymbolAddress((void**)&p_ahi,  g_ahi);  cudaGetSymbolAddress((void**)&p_alo, g_alo);
    cudaGetSymbolAddress((void**)&p_thi,  g_thi);  cudaGetSymbolAddress((void**)&p_tlo, g_tlo);
    cudaGetSymbolAddress((void**)&p_wqkvh, g_wqkvh); cudaGetSymbolAddress((void**)&p_wqkvl, g_wqkvl);
    cudaGetSymbolAddress((void**)&p_woh,   g_woh);   cudaGetSymbolAddress((void**)&p_wol,   g_wol);
    cudaGetSymbolAddress((void**)&p_w1h,   g_w1h);   cudaGetSymbolAddress((void**)&p_w1l,   g_w1l);
    cudaGetSymbolAddress((void**)&p_w2h,   g_w2h);   cudaGetSymbolAddress((void**)&p_w2l,   g_w2l);

    cudaFuncSetAttribute(k_gemm_mma, cudaFuncAttributeMaxDynamicSharedMemorySize, GSMEM);

    // weight conversion
    k_cvt<<<(786432 + 255)/256, 256>>>(Wqkv, p_wqkvh, p_wqkvl, 786432);
    k_cvt<<<(262144 + 255)/256, 256>>>(Wo,   p_woh,   p_wol,   262144);
    k_cvt<<<(1048576 + 255)/256, 256>>>(W1,  p_w1h,   p_w1l,   1048576);
    k_cvt<<<(1048576 + 255)/256, 256>>>(W2,  p_w2h,   p_w2l,   1048576);

    // embedding + graph
    k_embed<<<M_ROWS, 256>>>(x, Wfc, bfc, cls_tok, pos_emb, p_h, p_hhi, p_hlo);
    k_graph<<<1, 256>>>(emb1, emb2, Wl1, bl1, Wl2, bl2, p_a);

    for (int l = 0; l < LAYERS; l++) {
        if (l > 0) {
            k_extract<<<4096, 256>>>(p_h, p_X);
            k_prop<<<4096, 256>>>(p_a, p_X,  p_H1);
            k_prop<<<4096, 256>>>(p_a, p_H1, p_H2);
            k_mixout<<<4096, 256>>>(p_X, p_H1, p_H2,
                                    Wmlp + (size_t)(l-1)*256*768, bmlp + (l-1)*256,
                                    p_h, p_hhi, p_hlo);
        }
        // QKV
        k_gemm_mma<<<dim3(768/128, M_ROWS/128), 256, GSMEM>>>(
            p_hhi, p_hlo, p_wqkvh + (size_t)l*768*256, p_wqkvl + (size_t)l*768*256,
            bqkv + l*768, p_qkv, nullptr, nullptr, M_ROWS, 768, 256, 0);
        // attention
        k_attn<<<dim3(NH, SEQS), 128>>>(p_qkv, p_ahi, p_alo);
        // O-proj
        k_gemm_mma<<<dim3(256/128, M_ROWS/128), 256, GSMEM>>>(
            p_ahi, p_alo, p_woh + (size_t)l*256*256, p_wol + (size_t)l*256*256,
            bo + l*256, p_o, nullptr, nullptr, M_ROWS, 256, 256, 0);
        k_addln<<<M_ROWS, 256>>>(p_h, p_o, ln1g + l*256, ln1b + l*256, p_hhi, p_hlo);
        // FF1 (relu)
        k_gemm_mma<<<dim3(1024/128, M_ROWS/128), 256, GSMEM>>>(
            p_hhi, p_hlo, p_w1h + (size_t)l*1024*256, p_w1l + (size_t)l*1024*256,
            b1 + l*1024, nullptr, p_thi, p_tlo, M_ROWS, 1024, 256, 1);
        // FF2
        k_gemm_mma<<<dim3(256/128, M_ROWS/128), 256, GSMEM>>>(
            p_thi, p_tlo, p_w2h + (size_t)l*256*1024, p_w2l + (size_t)l*256*1024,
            b2 + l*256, p_o, nullptr, nullptr, M_ROWS, 256, 1024, 0);
        k_addln<<<M_ROWS, 256>>>(p_h, p_o, ln2g + l*256, ln2b + l*256, p_hhi, p_hlo);
    }

    // decoder
    k_dec1<<<BS, 256>>>(p_h, Wd1, bd1, p_d1);
    k_dec2<<<BS, 256>>>(p_d1, Wd2, bd2, out);
}